// round 12
// baseline (speedup 1.0000x reference)
#include <cuda_runtime.h>

#define B_ 8
#define N_ 8192
#define C_ 6
#define G_ 512
#define K_ 32

// Ascending FMA-chain sum of squares (KNN arithmetic — bitwise-verified).
__device__ __forceinline__ float sq3_fma(float a0, float a1, float a2) {
    float acc = __fmul_rn(a0, a0);
    acc = __fmaf_rn(a1, a1, acc);
    acc = __fmaf_rn(a2, a2, acc);
    return acc;
}

// Blackwell packed fp32x2 (bit-identical to the verified scalar chain).
#define ADD2(o, a, b) \
    asm("add.rn.f32x2 %0, %1, %2;" : "=l"(o) : "l"(a), "l"(b))
#define MUL2(o, a, b) \
    asm("mul.rn.f32x2 %0, %1, %2;" : "=l"(o) : "l"(a), "l"(b))
#define PACK2(o, lo, hi) \
    asm("mov.b64 %0, {%1, %2};" : "=l"(o) : "f"(lo), "f"(hi))
#define UNPACK2(lo, hi, v) \
    asm("mov.b64 {%0, %1}, %2;" : "=f"(lo), "=f"(hi) : "l"(v))

// ---------------------------------------------------------------------------
// FPS: one CTA per batch, 1024 threads, 8 pts/thread (f32x2-packed).
// NEW vs R7: the next centroid's xyz is forwarded through shared memory by
// the winning lane (which holds the point in registers) and distributed via
// ballot+shfl — the per-iteration global centroid LDG (L2 round trip on the
// critical path) is gone. Selection semantics unchanged: gm = max value,
// far = min index among ties (bit-exact).
// ---------------------------------------------------------------------------
__global__ void __launch_bounds__(1024) fps_kernel(
    const float* __restrict__ pts, float* __restrict__ center_out) {
    const int b    = blockIdx.x;
    const int tid  = threadIdx.x;
    const int lane = tid & 31;
    const int warp = tid >> 5;

    unsigned long long pxv[4], pyv[4], pzv[4];
    unsigned du[8];
    const float* base = pts + (size_t)b * N_ * C_;
#pragma unroll
    for (int j = 0; j < 4; j++) {
        const int p0 = tid + ((2 * j) << 10);
        const int p1 = tid + ((2 * j + 1) << 10);
        const float2 a01 = *(const float2*)(base + (size_t)p0 * C_);
        const float  a2  = base[(size_t)p0 * C_ + 2];
        const float2 b01 = *(const float2*)(base + (size_t)p1 * C_);
        const float  b2  = base[(size_t)p1 * C_ + 2];
        PACK2(pxv[j], a01.x, b01.x);
        PACK2(pyv[j], a01.y, b01.y);
        PACK2(pzv[j], a2, b2);
        du[2 * j]     = __float_as_uint(1e10f);
        du[2 * j + 1] = __float_as_uint(1e10f);
    }

    __shared__ unsigned s_wv[2][32];
    __shared__ int      s_wi[2][32];
    __shared__ float    s_wx[2][32];
    __shared__ float    s_wy[2][32];
    __shared__ float    s_wz[2][32];

    // g = 0 centroid: point 0 (single broadcast load, off the steady path)
    float cx = base[0], cy = base[1], cz = base[2];

    for (int g = 0; g < G_; g++) {
        const int par = g & 1;
        if (tid == 0) {
            float* co = center_out + ((size_t)b * G_ + g) * 3;
            co[0] = cx; co[1] = cy; co[2] = cz;
        }
        unsigned long long ncx, ncy, ncz;
        {
            const float nx = -cx, ny = -cy, nz = -cz;
            PACK2(ncx, nx, nx);
            PACK2(ncy, ny, ny);
            PACK2(ncz, nz, nz);
        }

        unsigned bmax = 0u;
#pragma unroll
        for (int j = 0; j < 4; j++) {
            unsigned long long dx, dy, dz, mx, my, mz, s1, d;
            ADD2(dx, pxv[j], ncx);          // x + (-c) == x - c, bit-exact
            ADD2(dy, pyv[j], ncy);
            ADD2(dz, pzv[j], ncz);
            MUL2(mx, dx, dx);
            MUL2(my, dy, dy);
            MUL2(mz, dz, dz);
            ADD2(s1, mx, my);
            ADD2(d, s1, mz);
            float d0, d1;
            UNPACK2(d0, d1, d);
            du[2 * j]     = umin(du[2 * j],     __float_as_uint(d0));
            du[2 * j + 1] = umin(du[2 * j + 1], __float_as_uint(d1));
            bmax = umax(bmax, umax(du[2 * j], du[2 * j + 1]));
        }
        int bi = 0x7fffffff, bj = 0;
#pragma unroll
        for (int j = 7; j >= 0; j--)
            if (du[j] == bmax) { bi = tid + (j << 10); bj = j; }

        const unsigned wmax = __reduce_max_sync(0xffffffffu, bmax);
        const int      wmin = __reduce_min_sync(
            0xffffffffu, (bmax == wmax) ? bi : 0x7fffffff);
        if (bmax == wmax && bi == wmin) {
            // winner lane publishes value, index, and the point's xyz
            float lx, hx, ly, hy, lz, hz;
            UNPACK2(lx, hx, pxv[bj >> 1]);
            UNPACK2(ly, hy, pyv[bj >> 1]);
            UNPACK2(lz, hz, pzv[bj >> 1]);
            s_wv[par][warp] = wmax;
            s_wi[par][warp] = wmin;
            s_wx[par][warp] = (bj & 1) ? hx : lx;
            s_wy[par][warp] = (bj & 1) ? hy : ly;
            s_wz[par][warp] = (bj & 1) ? hz : lz;
        }
        __syncthreads();  // the only barrier per iteration

        // every warp redundantly reduces the 32 per-warp partials
        const unsigned v = s_wv[par][lane];
        const int      i = s_wi[par][lane];
        const float    x = s_wx[par][lane];
        const float    y = s_wy[par][lane];
        const float    z = s_wz[par][lane];
        const unsigned gm  = __reduce_max_sync(0xffffffffu, v);
        const int      far = __reduce_min_sync(
            0xffffffffu, (v == gm) ? i : 0x7fffffff);
        // warp holding (gm, far) -> broadcast its xyz (bit-exact registers)
        const unsigned wb = __ballot_sync(0xffffffffu, v == gm && i == far);
        const int      w  = __ffs(wb) - 1;
        cx = __shfl_sync(0xffffffffu, x, w);
        cy = __shfl_sync(0xffffffffu, y, w);
        cz = __shfl_sync(0xffffffffu, z, w);
    }
}

// ---------------------------------------------------------------------------
// KNN + gather + center (R9 verbatim — verified, 83.5 us).
// ---------------------------------------------------------------------------
__global__ void __launch_bounds__(256) knn_kernel(
    const float* __restrict__ pts, const float* __restrict__ center_in,
    float* __restrict__ nbr_out) {
    __shared__ __align__(16) unsigned s_key[N_];
    __shared__ unsigned s_cmin[64];
    __shared__ int      s_sel[K_];
    __shared__ float    s_ctr[3];

    const int bg   = blockIdx.x;
    const int b    = bg >> 9;  // / G_
    const int tid  = threadIdx.x;
    const int lane = tid & 31;
    const int warp = tid >> 5;

    if (tid < 3) s_ctr[tid] = center_in[(size_t)bg * 3 + tid];
    __syncthreads();
    const float c0 = s_ctr[0], c1 = s_ctr[1], c2 = s_ctr[2];
    const float cc = sq3_fma(c0, c1, c2);

    const float* base = pts + (size_t)b * N_ * C_;

    // distance + chunk-min fused: warp w owns chunks [8w, 8w+8)
#pragma unroll
    for (int t = 0; t < 8; t++) {
        const int c = (warp << 3) + t;
        unsigned mloc = 0xffffffffu;
#pragma unroll
        for (int s = 0; s < 4; s++) {
            const int n = (c << 7) + lane + (s << 5);
            const float2 xy = *(const float2*)(base + (size_t)n * C_);
            const float x0 = xy.x, x1 = xy.y;
            const float x2 = base[(size_t)n * C_ + 2];
            const float xx = sq3_fma(x0, x1, x2);
            float dot = __fmul_rn(c0, x0);
            dot = __fmaf_rn(c1, x1, dot);
            dot = __fmaf_rn(c2, x2, dot);
            const float d2 =
                __fsub_rn(__fadd_rn(cc, xx), __fmul_rn(2.0f, dot));
            const unsigned bits = __float_as_uint(d2);
            const unsigned key =
                (bits & 0x80000000u) ? ~bits : (bits | 0x80000000u);
            s_key[n] = key;
            mloc = umin(mloc, key);
        }
        const unsigned cm = __reduce_min_sync(0xffffffffu, mloc);
        if (lane == 0) s_cmin[c] = cm;
    }
    __syncthreads();

    if (warp == 0) {
        unsigned a  = s_cmin[lane];
        unsigned bb = s_cmin[lane + 32];
        for (int k = 0; k < K_; k++) {
            const unsigned g  = __reduce_min_sync(0xffffffffu, umin(a, bb));
            const unsigned ba = __ballot_sync(0xffffffffu, a == g);
            const unsigned bB = __ballot_sync(0xffffffffu, bb == g);
            const unsigned c  = ba ? (unsigned)(__ffs(ba) - 1)
                                   : (unsigned)(__ffs(bB) - 1 + 32);

            const unsigned bi = (c << 7) + lane;
            unsigned v0 = s_key[bi];
            unsigned v1 = s_key[bi + 32];
            unsigned v2 = s_key[bi + 64];
            unsigned v3 = s_key[bi + 96];
            const unsigned m0 = __ballot_sync(0xffffffffu, v0 == g);
            const unsigned m1 = __ballot_sync(0xffffffffu, v1 == g);
            const unsigned m2 = __ballot_sync(0xffffffffu, v2 == g);
            const unsigned m3 = __ballot_sync(0xffffffffu, v3 == g);
            unsigned prel;
            if (m0)      prel = (unsigned)(__ffs(m0) - 1);
            else if (m1) prel = (unsigned)(__ffs(m1) - 1 + 32);
            else if (m2) prel = (unsigned)(__ffs(m2) - 1 + 64);
            else         prel = (unsigned)(__ffs(m3) - 1 + 96);
            const unsigned p = (c << 7) + prel;

            if (lane + 0u  == prel) v0 = 0xffffffffu;
            if (lane + 32u == prel) v1 = 0xffffffffu;
            if (lane + 64u == prel) v2 = 0xffffffffu;
            if (lane + 96u == prel) v3 = 0xffffffffu;
            const unsigned nm = __reduce_min_sync(
                0xffffffffu, umin(umin(v0, v1), umin(v2, v3)));

            if (lane == 0) {
                s_sel[k] = (int)p;
                s_key[p] = 0xffffffffu;
            }
            if (c == (unsigned)lane)            a  = nm;
            else if (c == (unsigned)lane + 32u) bb = nm;
            __syncwarp();
        }
    }
    __syncthreads();

    if (tid < K_ * C_) {
        const int k = tid / C_;
        const int c = tid % C_;
        const int i = s_sel[k];
        float v = base[(size_t)i * C_ + c];
        if (c < 3) v = __fsub_rn(v, s_ctr[c]);
        nbr_out[((size_t)bg * K_ + k) * C_ + c] = v;
    }
}

extern "C" void kernel_launch(void* const* d_in, const int* in_sizes, int n_in,
                              void* d_out, int out_size) {
    const float* pts = (const float*)d_in[0];
    float* out = (float*)d_out;
    float* center_out = out + (size_t)B_ * G_ * K_ * C_;

    fps_kernel<<<B_, 1024>>>(pts, center_out);
    knn_kernel<<<B_ * G_, 256>>>(pts, center_out, out);
}

// round 13
// speedup vs baseline: 1.5820x; 1.5820x over previous
#include <cuda_runtime.h>

#define B_ 8
#define N_ 8192
#define C_ 6
#define G_ 512
#define K_ 32

#define NCTAS 148          // one CTA per SM (bids 0..147 -> distinct SMs)
#define NTASKS (B_ * G_)   // 4096 knn tasks

__device__ int g_flag[B_ * 32];  // padded: one 128-B line per batch
__device__ int g_ctr;

// Ascending FMA-chain sum of squares (KNN arithmetic — bitwise-verified).
__device__ __forceinline__ float sq3_fma(float a0, float a1, float a2) {
    float acc = __fmul_rn(a0, a0);
    acc = __fmaf_rn(a1, a1, acc);
    acc = __fmaf_rn(a2, a2, acc);
    return acc;
}

// Blackwell packed fp32x2 (bit-identical to the verified scalar chain).
#define ADD2(o, a, b) \
    asm("add.rn.f32x2 %0, %1, %2;" : "=l"(o) : "l"(a), "l"(b))
#define MUL2(o, a, b) \
    asm("mul.rn.f32x2 %0, %1, %2;" : "=l"(o) : "l"(a), "l"(b))
#define PACK2(o, lo, hi) \
    asm("mov.b64 %0, {%1, %2};" : "=l"(o) : "f"(lo), "f"(hi))
#define UNPACK2(lo, hi, v) \
    asm("mov.b64 {%0, %1}, %2;" : "=f"(lo), "=f"(hi) : "l"(v))

union SmemU {
    struct {
        unsigned wv[2][32];
        int      wi[2][32];
    } fps;
    struct {
        unsigned key[N_];
        unsigned cmin[64];
        int      sel[K_];
        float    ctr[3];
        int      task;
    } knn;
};

__global__ void __launch_bounds__(256) reset_kernel() {
    g_flag[threadIdx.x] = 0;
    if (threadIdx.x == 0) g_ctr = 0;
}

__global__ void __launch_bounds__(1024) fused_kernel(
    const float* __restrict__ pts, float* __restrict__ nbr_out,
    float* __restrict__ center_out) {
    __shared__ SmemU u;

    const int bid  = blockIdx.x;
    const int tid  = threadIdx.x;
    const int lane = tid & 31;
    const int warp = tid >> 5;

    if (bid < B_) {
        // ============ FPS (R9-verified bytes + amortized publish) ============
        const int b = bid;
        unsigned long long pxv[4], pyv[4], pzv[4];
        unsigned du[8];
        const float* base = pts + (size_t)b * N_ * C_;
#pragma unroll
        for (int j = 0; j < 4; j++) {
            const int p0 = tid + ((2 * j) << 10);
            const int p1 = tid + ((2 * j + 1) << 10);
            const float2 a01 = *(const float2*)(base + (size_t)p0 * C_);
            const float  a2  = base[(size_t)p0 * C_ + 2];
            const float2 b01 = *(const float2*)(base + (size_t)p1 * C_);
            const float  b2  = base[(size_t)p1 * C_ + 2];
            PACK2(pxv[j], a01.x, b01.x);
            PACK2(pyv[j], a01.y, b01.y);
            PACK2(pzv[j], a2, b2);
            du[2 * j]     = __float_as_uint(1e10f);
            du[2 * j + 1] = __float_as_uint(1e10f);
        }

        int far = 0;
        for (int g = 0; g < G_; g++) {
            const int par = g & 1;
            const float* cq = base + (size_t)far * C_;
            const float2 cxy = *(const float2*)cq;
            const float cx = cxy.x, cy = cxy.y, cz = cq[2];
            if (tid == 0) {
                float* co = center_out + ((size_t)b * G_ + g) * 3;
                co[0] = cx; co[1] = cy; co[2] = cz;
                if ((g & 3) == 3)  // publish centers 0..g (g=3,7,...,511)
                    asm volatile("st.release.gpu.global.b32 [%0], %1;"
                                 :: "l"(&g_flag[b * 32]), "r"(g + 1)
                                 : "memory");
            }
            unsigned long long ncx, ncy, ncz;
            {
                const float nx = -cx, ny = -cy, nz = -cz;
                PACK2(ncx, nx, nx);
                PACK2(ncy, ny, ny);
                PACK2(ncz, nz, nz);
            }

            unsigned bmax = 0u;
#pragma unroll
            for (int j = 0; j < 4; j++) {
                unsigned long long dx, dy, dz, mx, my, mz, s1, d;
                ADD2(dx, pxv[j], ncx);   // x + (-c) == x - c, bit-exact
                ADD2(dy, pyv[j], ncy);
                ADD2(dz, pzv[j], ncz);
                MUL2(mx, dx, dx);
                MUL2(my, dy, dy);
                MUL2(mz, dz, dz);
                ADD2(s1, mx, my);
                ADD2(d, s1, mz);
                float d0, d1;
                UNPACK2(d0, d1, d);
                du[2 * j]     = umin(du[2 * j],     __float_as_uint(d0));
                du[2 * j + 1] = umin(du[2 * j + 1], __float_as_uint(d1));
                bmax = umax(bmax, umax(du[2 * j], du[2 * j + 1]));
            }
            int bi = 0x7fffffff;
#pragma unroll
            for (int j = 7; j >= 0; j--)
                if (du[j] == bmax) bi = tid + (j << 10);

            const unsigned wmax = __reduce_max_sync(0xffffffffu, bmax);
            const int      wmin = __reduce_min_sync(
                0xffffffffu, (bmax == wmax) ? bi : 0x7fffffff);
            if (lane == 0) {
                u.fps.wv[par][warp] = wmax;
                u.fps.wi[par][warp] = wmin;
            }
            __syncthreads();  // the only barrier per iteration

            const unsigned v = u.fps.wv[par][lane];
            const int      i = u.fps.wi[par][lane];
            const unsigned gm = __reduce_max_sync(0xffffffffu, v);
            far = __reduce_min_sync(0xffffffffu, (v == gm) ? i : 0x7fffffff);
        }
        return;
    }

    // ============ persistent KNN worker (R10-verified task body) ============
    for (;;) {
        if (tid == 0) u.knn.task = atomicAdd(&g_ctr, 1);
        __syncthreads();
        const int t = u.knn.task;
        if (t >= NTASKS) break;
        const int b  = t & 7;       // g-major: consume in publish order
        const int g  = t >> 3;
        const int bg = (b << 9) + g;

        if (tid == 0) {
            int v;
            do {
                asm volatile("ld.acquire.gpu.global.b32 %0, [%1];"
                             : "=r"(v) : "l"(&g_flag[b * 32]) : "memory");
                if (v > g) break;
                __nanosleep(128);
            } while (true);
        }
        __syncthreads();

        if (tid < 3) u.knn.ctr[tid] = center_out[(size_t)bg * 3 + tid];
        __syncthreads();
        const float c0 = u.knn.ctr[0], c1 = u.knn.ctr[1], c2 = u.knn.ctr[2];
        const float cc = sq3_fma(c0, c1, c2);

        const float* base = pts + (size_t)b * N_ * C_;

        // distance + chunk-min fused: warp w owns chunks {2w, 2w+1}
#pragma unroll
        for (int tt = 0; tt < 2; tt++) {
            const int c = (warp << 1) + tt;
            unsigned mloc = 0xffffffffu;
#pragma unroll
            for (int s = 0; s < 4; s++) {
                const int n = (c << 7) + lane + (s << 5);
                const float2 xy = *(const float2*)(base + (size_t)n * C_);
                const float x0 = xy.x, x1 = xy.y;
                const float x2 = base[(size_t)n * C_ + 2];
                const float xx = sq3_fma(x0, x1, x2);
                float dot = __fmul_rn(c0, x0);
                dot = __fmaf_rn(c1, x1, dot);
                dot = __fmaf_rn(c2, x2, dot);
                const float d2 =
                    __fsub_rn(__fadd_rn(cc, xx), __fmul_rn(2.0f, dot));
                const unsigned bits = __float_as_uint(d2);
                const unsigned key =
                    (bits & 0x80000000u) ? ~bits : (bits | 0x80000000u);
                u.knn.key[n] = key;
                mloc = umin(mloc, key);
            }
            const unsigned cm = __reduce_min_sync(0xffffffffu, mloc);
            if (lane == 0) u.knn.cmin[c] = cm;
        }
        __syncthreads();

        if (warp == 0) {
            unsigned a  = u.knn.cmin[lane];
            unsigned bb = u.knn.cmin[lane + 32];
            for (int k = 0; k < K_; k++) {
                const unsigned gmin =
                    __reduce_min_sync(0xffffffffu, umin(a, bb));
                const unsigned ba = __ballot_sync(0xffffffffu, a == gmin);
                const unsigned bB = __ballot_sync(0xffffffffu, bb == gmin);
                const unsigned c  = ba ? (unsigned)(__ffs(ba) - 1)
                                       : (unsigned)(__ffs(bB) - 1 + 32);

                const unsigned bi = (c << 7) + lane;
                unsigned v0 = u.knn.key[bi];
                unsigned v1 = u.knn.key[bi + 32];
                unsigned v2 = u.knn.key[bi + 64];
                unsigned v3 = u.knn.key[bi + 96];
                const unsigned m0 = __ballot_sync(0xffffffffu, v0 == gmin);
                const unsigned m1 = __ballot_sync(0xffffffffu, v1 == gmin);
                const unsigned m2 = __ballot_sync(0xffffffffu, v2 == gmin);
                const unsigned m3 = __ballot_sync(0xffffffffu, v3 == gmin);
                unsigned prel;
                if (m0)      prel = (unsigned)(__ffs(m0) - 1);
                else if (m1) prel = (unsigned)(__ffs(m1) - 1 + 32);
                else if (m2) prel = (unsigned)(__ffs(m2) - 1 + 64);
                else         prel = (unsigned)(__ffs(m3) - 1 + 96);
                const unsigned p = (c << 7) + prel;

                if (lane + 0u  == prel) v0 = 0xffffffffu;
                if (lane + 32u == prel) v1 = 0xffffffffu;
                if (lane + 64u == prel) v2 = 0xffffffffu;
                if (lane + 96u == prel) v3 = 0xffffffffu;
                const unsigned nm = __reduce_min_sync(
                    0xffffffffu, umin(umin(v0, v1), umin(v2, v3)));

                if (lane == 0) {
                    u.knn.sel[k] = (int)p;
                    u.knn.key[p] = 0xffffffffu;
                }
                if (c == (unsigned)lane)            a  = nm;
                else if (c == (unsigned)lane + 32u) bb = nm;
                __syncwarp();
            }
        }
        __syncthreads();

        if (tid < K_ * C_) {
            const int k = tid / C_;
            const int c = tid % C_;
            const int i = u.knn.sel[k];
            float v = base[(size_t)i * C_ + c];
            if (c < 3) v = __fsub_rn(v, u.knn.ctr[c]);
            nbr_out[((size_t)bg * K_ + k) * C_ + c] = v;
        }
        // loop-top __syncthreads orders smem reuse for the next task
    }
}

extern "C" void kernel_launch(void* const* d_in, const int* in_sizes, int n_in,
                              void* d_out, int out_size) {
    const float* pts = (const float*)d_in[0];
    float* out = (float*)d_out;
    float* center_out = out + (size_t)B_ * G_ * K_ * C_;

    reset_kernel<<<1, 256>>>();
    fused_kernel<<<NCTAS, 1024>>>(pts, out, center_out);
}